// round 10
// baseline (speedup 1.0000x reference)
#include <cuda_runtime.h>
#include <cstdint>
#include <math.h>

#define T_LEN 2048
#define BATCH 32
#define DIN   256
#define HID   256
#define NG    1024   // 4*HID
#define AOUT  18
#define CLC   8      // CTAs per cluster
#define GBLK  128    // 16 clusters x 8 CTAs
#define TXB   3584   // 7 peers x 64 threads x 8B per phase

typedef unsigned long long ull;

// ---------------- device scratch (no allocs allowed) ----------------
__device__ float g_Gx[(size_t)T_LEN * BATCH * NG];   // [r = t*32+b][n]  (256 MiB)

// packed f32x2 FMA (SASS FFMA2): 2 fp32 FMAs per instruction
__device__ __forceinline__ ull fma2(ull a, ull b, ull c) {
    ull d;
    asm("fma.rn.f32x2 %0, %1, %2, %3;" : "=l"(d) : "l"(a), "l"(b), "l"(c));
    return d;
}
__device__ __forceinline__ ull dupf(float v) {
    unsigned u = __float_as_uint(v);
    return (ull)u | ((ull)u << 32);
}
__device__ __forceinline__ float sigm(float z) { return 1.f / (1.f + __expf(-z)); }
__device__ __forceinline__ float tanh_e(float z) { return 2.f / (1.f + __expf(-2.f * z)) - 1.f; }

__device__ __forceinline__ unsigned smem_u32(const void* p) {
    unsigned a;
    asm("{ .reg .u64 t; cvta.to.shared.u64 t, %1; cvt.u32.u64 %0, t; }"
        : "=r"(a) : "l"(p));
    return a;
}

__device__ __forceinline__ void mbar_init(unsigned mb, unsigned cnt) {
    asm volatile("mbarrier.init.shared.b64 [%0], %1;" :: "r"(mb), "r"(cnt) : "memory");
}
__device__ __forceinline__ void mbar_expect(unsigned mb, unsigned tx) {
    asm volatile("mbarrier.arrive.expect_tx.shared.b64 _, [%0], %1;"
                 :: "r"(mb), "r"(tx) : "memory");
}
__device__ __forceinline__ void mbar_wait(unsigned mb, unsigned parity) {
    unsigned done;
    do {
        asm volatile(
            "{ .reg .pred p;\n\t"
            "mbarrier.try_wait.parity.acquire.cluster.shared::cta.b64 p, [%1], %2, 0x989680;\n\t"
            "selp.b32 %0, 1, 0, p; }"
            : "=r"(done) : "r"(mb), "r"(parity) : "memory");
    } while (!done);
}

// =====================================================================
// Phase 1: Gx[r][n] = (x@W[0:256,:])[r, n] + bias[n],  r = t*32 + b
// (unchanged control)
// =====================================================================
__global__ void __launch_bounds__(256) gemm_x(const float* __restrict__ x,
                                              const float* __restrict__ W,
                                              const float* __restrict__ bias) {
    __shared__ float As[2][16 * 128];
    __shared__ float Bsd[2][16 * 128];

    int tid = threadIdx.x;
    int mt = tid & 15, nt = tid >> 4;
    int rbase = blockIdx.y * 128;
    int nb = blockIdx.x * 64;

    int row = tid >> 1, half = tid & 1;
    int rr = rbase + row;
    int bB = rr & 31, tT = rr >> 5;
    const float* xbase = x + ((size_t)bB * T_LEN + tT) * DIN + half * 8;
    int wk = tid >> 4, wn = (tid & 15) * 4;
    const float* wbase = W + (size_t)wk * NG + nb + wn;

    float4 xa, xb, wv;
    ull acc[4][4];
#pragma unroll
    for (int i = 0; i < 4; ++i)
#pragma unroll
        for (int j = 0; j < 4; ++j) acc[i][j] = 0ull;

    xa = *(const float4*)(xbase);
    xb = *(const float4*)(xbase + 4);
    wv = *(const float4*)(wbase);

#define STASH(buf)                                                       \
    {                                                                    \
        float* A = As[buf];                                              \
        int ko = half * 8;                                               \
        A[(ko + 0) * 128 + row] = xa.x; A[(ko + 1) * 128 + row] = xa.y;  \
        A[(ko + 2) * 128 + row] = xa.z; A[(ko + 3) * 128 + row] = xa.w;  \
        A[(ko + 4) * 128 + row] = xb.x; A[(ko + 5) * 128 + row] = xb.y;  \
        A[(ko + 6) * 128 + row] = xb.z; A[(ko + 7) * 128 + row] = xb.w;  \
        float* Bd = Bsd[buf];                                            \
        float4 d0 = make_float4(wv.x, wv.x, wv.y, wv.y);                 \
        float4 d1 = make_float4(wv.z, wv.z, wv.w, wv.w);                 \
        *(float4*)&Bd[wk * 128 + wn * 2]     = d0;                       \
        *(float4*)&Bd[wk * 128 + wn * 2 + 4] = d1;                       \
    }

    STASH(0);
    __syncthreads();

    for (int kt = 0; kt < 16; ++kt) {
        int buf = kt & 1;
        if (kt < 15) {
            xa = *(const float4*)(xbase + (kt + 1) * 16);
            xb = *(const float4*)(xbase + (kt + 1) * 16 + 4);
            wv = *(const float4*)(wbase + (size_t)(kt + 1) * 16 * NG);
        }
        const float* A = As[buf];
        const float* Bd = Bsd[buf];
#pragma unroll
        for (int k = 0; k < 16; ++k) {
            ulonglong2 a01 = *(const ulonglong2*)&A[k * 128 + mt * 8];
            ulonglong2 a23 = *(const ulonglong2*)&A[k * 128 + mt * 8 + 4];
            ulonglong2 b01 = *(const ulonglong2*)&Bd[k * 128 + nt * 8];
            ulonglong2 b23 = *(const ulonglong2*)&Bd[k * 128 + nt * 8 + 4];
            ull am[4] = {a01.x, a01.y, a23.x, a23.y};
            ull bd[4] = {b01.x, b01.y, b23.x, b23.y};
#pragma unroll
            for (int mp = 0; mp < 4; ++mp)
#pragma unroll
                for (int nn = 0; nn < 4; ++nn)
                    acc[mp][nn] = fma2(am[mp], bd[nn], acc[mp][nn]);
        }
        if (kt < 15) {
            STASH(buf ^ 1);
            __syncthreads();
        }
    }
#undef STASH

    float4 bv = *(const float4*)&bias[nb + nt * 4];
#pragma unroll
    for (int mp = 0; mp < 4; ++mp) {
        int r = rbase + mt * 8 + mp * 2;
        float2 v0 = *(float2*)&acc[mp][0];
        float2 v1 = *(float2*)&acc[mp][1];
        float2 v2 = *(float2*)&acc[mp][2];
        float2 v3 = *(float2*)&acc[mp][3];
        float4 o0 = make_float4(v0.x + bv.x, v1.x + bv.y, v2.x + bv.z, v3.x + bv.w);
        float4 o1 = make_float4(v0.y + bv.x, v1.y + bv.y, v2.y + bv.z, v3.y + bv.w);
        *(float4*)&g_Gx[(size_t)r * NG + nb + nt * 4]       = o0;
        *(float4*)&g_Gx[(size_t)(r + 1) * NG + nb + nt * 4] = o1;
    }
}

// =====================================================================
// Phase 2: clustered recurrence with st.async + mbarrier tx sync.
// Cluster (8 CTAs) owns 2 batches; CTA rank owns h-cols [32r,32r+32).
// Weights register-stationary. h published via st.async (tx-counted);
// consumers wake on their local mbarrier — no barrier.cluster in loop.
// =====================================================================
__global__ void __launch_bounds__(256, 1) __cluster_dims__(CLC, 1, 1)
lstm_rec(const float* __restrict__ W,
         const int* __restrict__ seq_lens,
         const float* __restrict__ c_in,
         const float* __restrict__ h_in,
         float* __restrict__ out) {
    __shared__ __align__(16) ull hsd[2][HID][2];   // duplicated h pairs, 8KB
    __shared__ __align__(16) ull part[8][32][4];   // k-partials, 8KB
    __shared__ float gred[2][128];                 // reduced gates [b][gc]
    __shared__ __align__(8) ull mbars[2];          // tx barriers (buf 0/1)

    int tid = threadIdx.x;
    int lane = tid & 31, wrp = tid >> 5;
    unsigned rank;
    asm("mov.u32 %0, %%cluster_ctarank;" : "=r"(rank));
    int cid = blockIdx.x >> 3;
    int b0 = cid * 2;

    unsigned mb0 = smem_u32(&mbars[0]);
    unsigned mb1 = smem_u32(&mbars[1]);

    // ---- weight-stationary registers: 32 k x 4 gate cols per thread ----
    ull wreg[32][2];
    {
        int gc4 = lane * 4;
        int n = (gc4 >> 5) * 256 + (int)rank * 32 + (gc4 & 31);
#pragma unroll
        for (int kk = 0; kk < 32; ++kk) {
            int k = wrp * 32 + kk;
            float4 w4 = *(const float4*)&W[(size_t)(DIN + k) * NG + n];
            float2 p0 = make_float2(w4.x, w4.y);
            float2 p1 = make_float2(w4.z, w4.w);
            wreg[kk][0] = *(ull*)&p0;
            wreg[kk][1] = *(ull*)&p1;
        }
    }

    // ---- init hsd[0] with full h(0) (local copy) + mbarriers ----
    {
        int k = tid;
        hsd[0][k][0] = dupf(h_in[b0 * HID + k]);
        hsd[0][k][1] = dupf(h_in[(b0 + 1) * HID + k]);
    }
    if (tid == 0) {
        mbar_init(mb0, 1);
        mbar_init(mb1, 1);
    }

    // ---- act-thread state (tid < 64): (hl, bb) ----
    int hl = tid & 31, bb = tid >> 5;
    int n_act = (int)rank * 32 + hl;
    float creg = 0.f, hreg = 0.f;
    int slen = 0;
    if (tid < 64) {
        creg = c_in[(b0 + bb) * HID + n_act];
        hreg = h_in[(b0 + bb) * HID + n_act];
        slen = seq_lens[b0 + bb];
    }
    __syncthreads();
    // mbarriers + hsd[0] visible cluster-wide before any peer st.async
    asm volatile("barrier.cluster.arrive.aligned;" ::: "memory");
    asm volatile("barrier.cluster.wait.aligned;" ::: "memory");

    if (tid == 0) {            // pre-arm phase 0 of both barriers
        mbar_expect(mb1, TXB);   // receives h(1), consumed at t=1
        mbar_expect(mb0, TXB);   // receives h(2), consumed at t=2
    }

    float* outLL = out + (size_t)BATCH * T_LEN * AOUT;
    unsigned laddr0 = smem_u32(&hsd[0][n_act][bb]);
    unsigned laddr1 = smem_u32(&hsd[1][n_act][bb]);

    // prefetch Gx(0) into regs (one-step-ahead double buffer)
    float ga0 = 0.f, ga1 = 0.f, ga2 = 0.f, ga3 = 0.f;
    float gb0 = 0.f, gb1 = 0.f, gb2 = 0.f, gb3 = 0.f;
    const float* gxbase = g_Gx;
    if (tid < 64) {
        const float* gp = g_Gx + ((size_t)(b0 + bb)) * NG + n_act;
        ga0 = gp[0]; ga1 = gp[256]; ga2 = gp[512]; ga3 = gp[768];
    }

#pragma unroll 1
    for (int t = 0; t < T_LEN; ++t) {
        int cur = t & 1;
        int nxt = cur ^ 1;

        if (t > 0) {
            if (tid == 0) {
                mbar_wait(cur ? mb1 : mb0, ((unsigned)(t - 1) >> 1) & 1u);
                if (t + 2 < T_LEN)
                    mbar_expect(cur ? mb1 : mb0, TXB);   // re-arm for h(t+2)
            }
            __syncthreads();
        }

        // issue next step's Gx loads (consumed at t+1 -> full step of hiding)
        if (tid < 64) {
            int tn = (t + 1 < T_LEN) ? (t + 1) : t;
            const float* gp = g_Gx + ((size_t)(tn * 32 + b0 + bb)) * NG + n_act;
            gb0 = gp[0]; gb1 = gp[256]; gb2 = gp[512]; gb3 = gp[768];
        }

        // ---- h @ Wh: register weights, broadcast LDS of duplicated h ----
        ull a0 = 0, a1 = 0, a2 = 0, a3 = 0;
#pragma unroll
        for (int kk = 0; kk < 32; ++kk) {
            int k = wrp * 32 + kk;
            ulonglong2 h2 = *(const ulonglong2*)&hsd[cur][k][0];
            a0 = fma2(h2.x, wreg[kk][0], a0);
            a1 = fma2(h2.x, wreg[kk][1], a1);
            a2 = fma2(h2.y, wreg[kk][0], a2);
            a3 = fma2(h2.y, wreg[kk][1], a3);
        }
        ulonglong2 s01 = {a0, a1};
        ulonglong2 s23 = {a2, a3};
        *(ulonglong2*)&part[wrp][lane][0] = s01;
        *(ulonglong2*)&part[wrp][lane][2] = s23;
        __syncthreads();

        // ---- cross-warp k-reduction ----
        {
            int l = tid >> 3, c = (tid >> 1) & 3, h = tid & 1;
            float s = 0.f;
#pragma unroll
            for (int w = 0; w < 8; ++w)
                s += ((const float*)&part[w][l][c])[h];
            int gc = 4 * l + 2 * (c & 1) + h;
            gred[c >> 1][gc] = s;
        }
        __syncthreads();

        // ---- activations + state update + st.async publish ----
        if (tid < 64) {
            float gi = gred[bb][hl]      + ga0;
            float gj = gred[bb][32 + hl] + ga1;
            float gf = gred[bb][64 + hl] + ga2;
            float go = gred[bb][96 + hl] + ga3;
            float sf = sigm(gf + 1.f);   // FORGET_BIAS = 1
            float si = sigm(gi);
            float so = sigm(go);
            float nc = creg * sf + si * tanh_e(gj);
            float nh = tanh_e(nc) * so;
            bool mvalid = (t < slen);
            if (mvalid) { creg = nc; hreg = nh; }

            if (t + 1 < T_LEN) {
                ull hv = dupf(hreg);
                unsigned la = nxt ? laddr1 : laddr0;
                unsigned mbl = nxt ? mb1 : mb0;
#pragma unroll
                for (int pr = 0; pr < CLC; ++pr) {
                    if (pr == (int)rank) {
                        asm volatile("st.shared.b64 [%0], %1;"
                                     :: "r"(la), "l"(hv) : "memory");
                    } else {
                        unsigned da, ma;
                        asm volatile("mapa.shared::cluster.u32 %0, %1, %2;"
                                     : "=r"(da) : "r"(la), "r"(pr));
                        asm volatile("mapa.shared::cluster.u32 %0, %1, %2;"
                                     : "=r"(ma) : "r"(mbl), "r"(pr));
                        asm volatile(
                            "st.async.weak.shared::cluster.mbarrier::complete_tx::bytes.b64 [%0], %1, [%2];"
                            :: "r"(da), "l"(hv), "r"(ma) : "memory");
                    }
                }
            }

            // off critical path:
            outLL[((size_t)(b0 + bb) * T_LEN + t) * HID + n_act] = mvalid ? nh : 0.f;
            ga0 = gb0; ga1 = gb1; ga2 = gb2; ga3 = gb3;
        }
    }

    if (tid < 64) {   // finals
        float* cf = out + (size_t)BATCH * T_LEN * AOUT + (size_t)BATCH * T_LEN * HID;
        float* hf = cf + BATCH * HID;
        cf[(b0 + bb) * HID + n_act] = creg;
        hf[(b0 + bb) * HID + n_act] = hreg;
    }

    // all phases balanced; final cluster sync before exit
    asm volatile("barrier.cluster.arrive.aligned;" ::: "memory");
    asm volatile("barrier.cluster.wait.aligned;" ::: "memory");
}

// =====================================================================
// Phase 3: logits = last_layer @ W_out + b_out.
// =====================================================================
#define PROJ_TPB 288
__global__ void __launch_bounds__(PROJ_TPB) proj_kernel(const float* __restrict__ LL,
                                                        const float* __restrict__ Wo,
                                                        const float* __restrict__ bo,
                                                        float* __restrict__ logits,
                                                        int tiles_per_block) {
    __shared__ float Wsm[256 * 18];
    __shared__ float Lsm[16 * 257];

    int tid = threadIdx.x;
    for (int i = tid; i < 256 * 18; i += PROJ_TPB) Wsm[i] = Wo[i];
    int r = tid / 18;
    int a = tid - r * 18;
    float bv = bo[a];

    for (int tile = 0; tile < tiles_per_block; ++tile) {
        int rbase = (blockIdx.x * tiles_per_block + tile) * 16;
        __syncthreads();
        for (int i = tid; i < 16 * 256; i += PROJ_TPB) {
            int rr = i >> 8, c = i & 255;
            Lsm[rr * 257 + c] = LL[(size_t)rbase * 256 + i];
        }
        __syncthreads();
        float acc = 0.f;
        const float* lr = &Lsm[r * 257];
#pragma unroll 8
        for (int h = 0; h < 256; ++h)
            acc = fmaf(lr[h], Wsm[h * 18 + a], acc);
        logits[(size_t)(rbase + r) * AOUT + a] = acc + bv;
    }
}

// =====================================================================
extern "C" void kernel_launch(void* const* d_in, const int* in_sizes, int n_in,
                              void* d_out, int out_size) {
    const float* x        = (const float*)d_in[0];
    const int*   seq_lens = (const int*)  d_in[1];
    const float* c_in     = (const float*)d_in[2];
    const float* h_in     = (const float*)d_in[3];
    const float* W        = (const float*)d_in[4];
    const float* b        = (const float*)d_in[5];
    const float* W_out    = (const float*)d_in[6];
    const float* b_out    = (const float*)d_in[7];
    float* out = (float*)d_out;

    // Phase 1: input GEMM for all timesteps
    gemm_x<<<dim3(16, 512), 256>>>(x, W, b);

    // Phase 2: clustered recurrence (writes last_layer, c_fin, h_fin)
    lstm_rec<<<GBLK, 256>>>(W, seq_lens, c_in, h_in, out);

    // Phase 3: output projection (reads last_layer from out)
    const float* LL = out + (size_t)BATCH * T_LEN * AOUT;
    proj_kernel<<<512, PROJ_TPB>>>(LL, W_out, b_out, out, 8);
}

// round 11
// speedup vs baseline: 1.0544x; 1.0544x over previous
#include <cuda_runtime.h>
#include <cstdint>
#include <math.h>

#define T_LEN 2048
#define BATCH 32
#define DIN   256
#define HID   256
#define NG    1024   // 4*HID
#define AOUT  18
#define CLC   8      // CTAs per cluster
#define GBLK  128    // 16 clusters x 8 CTAs

typedef unsigned long long ull;

// ---------------- device scratch (no allocs allowed) ----------------
__device__ float g_Gx[(size_t)T_LEN * BATCH * NG];   // [r = t*32+b][n]  (256 MiB)

// packed f32x2 FMA (SASS FFMA2): 2 fp32 FMAs per instruction
__device__ __forceinline__ ull fma2(ull a, ull b, ull c) {
    ull d;
    asm("fma.rn.f32x2 %0, %1, %2, %3;" : "=l"(d) : "l"(a), "l"(b), "l"(c));
    return d;
}
__device__ __forceinline__ ull dupf(float v) {
    unsigned u = __float_as_uint(v);
    return (ull)u | ((ull)u << 32);
}
__device__ __forceinline__ float sigm(float z) { return 1.f / (1.f + __expf(-z)); }
__device__ __forceinline__ float tanh_e(float z) { return 2.f / (1.f + __expf(-2.f * z)) - 1.f; }

__device__ __forceinline__ unsigned smem_u32(const void* p) {
    unsigned a;
    asm("{ .reg .u64 t; cvta.to.shared.u64 t, %1; cvt.u32.u64 %0, t; }"
        : "=r"(a) : "l"(p));
    return a;
}

// =====================================================================
// Phase 1: Gx[r][n] = (x@W[0:256,:])[r, n] + bias[n],  r = t*32 + b
// NEW: block tile 128m x 128n, ktile 8, thread tile 8m x 8n (32 FFMA2
// per 6 LDS.128), double-buffered smem, 2 CTAs/SM.
// =====================================================================
__global__ void __launch_bounds__(256, 2) gemm_x(const float* __restrict__ x,
                                                 const float* __restrict__ W,
                                                 const float* __restrict__ bias) {
    __shared__ float As[2][8 * 128];    // [k][m]           4KB x2
    __shared__ float Bsd[2][8 * 256];   // [k][n dup x2]    8KB x2

    int tid = threadIdx.x;
    int mt = tid & 15, nt = tid >> 4;   // 16 x 16 thread grid
    int rbase = blockIdx.y * 128;
    int nb = blockIdx.x * 128;

    // A staging: 2 threads per row, 4 k each
    int row = tid >> 1, half = tid & 1;
    int rr = rbase + row;
    int bB = rr & 31, tT = rr >> 5;
    const float* xbase = x + ((size_t)bB * T_LEN + tT) * DIN + half * 4;
    // B staging: 8 k rows x 128 n / 4 per thread
    int wk = tid >> 5, wn = (tid & 31) * 4;
    const float* wbase = W + (size_t)wk * NG + nb + wn;

    float4 xa, wv;
    ull acc[4][8];
#pragma unroll
    for (int i = 0; i < 4; ++i)
#pragma unroll
        for (int j = 0; j < 8; ++j) acc[i][j] = 0ull;

    xa = *(const float4*)(xbase);
    wv = *(const float4*)(wbase);

#define STASH(buf)                                                        \
    {                                                                     \
        float* A = As[buf];                                               \
        int ko = half * 4;                                                \
        A[(ko + 0) * 128 + row] = xa.x; A[(ko + 1) * 128 + row] = xa.y;   \
        A[(ko + 2) * 128 + row] = xa.z; A[(ko + 3) * 128 + row] = xa.w;   \
        float* Bd = Bsd[buf];                                             \
        float4 d0 = make_float4(wv.x, wv.x, wv.y, wv.y);                  \
        float4 d1 = make_float4(wv.z, wv.z, wv.w, wv.w);                  \
        *(float4*)&Bd[wk * 256 + wn * 2]     = d0;                        \
        *(float4*)&Bd[wk * 256 + wn * 2 + 4] = d1;                        \
    }

    STASH(0);
    __syncthreads();

    for (int kt = 0; kt < 32; ++kt) {   // 32 ktiles of 8
        int buf = kt & 1;
        if (kt < 31) {   // prefetch next ktile (overlaps with compute)
            xa = *(const float4*)(xbase + (kt + 1) * 8);
            wv = *(const float4*)(wbase + (size_t)(kt + 1) * 8 * NG);
        }
        const float* A = As[buf];
        const float* Bd = Bsd[buf];
#pragma unroll
        for (int k = 0; k < 8; ++k) {
            ulonglong2 a01 = *(const ulonglong2*)&A[k * 128 + mt * 8];
            ulonglong2 a23 = *(const ulonglong2*)&A[k * 128 + mt * 8 + 4];
            ulonglong2 b01 = *(const ulonglong2*)&Bd[k * 256 + nt * 16];
            ulonglong2 b23 = *(const ulonglong2*)&Bd[k * 256 + nt * 16 + 4];
            ulonglong2 b45 = *(const ulonglong2*)&Bd[k * 256 + nt * 16 + 8];
            ulonglong2 b67 = *(const ulonglong2*)&Bd[k * 256 + nt * 16 + 12];
            ull am[4] = {a01.x, a01.y, a23.x, a23.y};
            ull bd[8] = {b01.x, b01.y, b23.x, b23.y, b45.x, b45.y, b67.x, b67.y};
#pragma unroll
            for (int mp = 0; mp < 4; ++mp)
#pragma unroll
                for (int nn = 0; nn < 8; ++nn)
                    acc[mp][nn] = fma2(am[mp], bd[nn], acc[mp][nn]);
        }
        if (kt < 31) {
            STASH(buf ^ 1);
            __syncthreads();
        }
    }
#undef STASH

    // epilogue: 8 rows x 8 n per thread, bias added, row-major [r][n]
    float4 bv0 = *(const float4*)&bias[nb + nt * 8];
    float4 bv1 = *(const float4*)&bias[nb + nt * 8 + 4];
#pragma unroll
    for (int mp = 0; mp < 4; ++mp) {
#pragma unroll
        for (int h = 0; h < 2; ++h) {
            int r = rbase + mt * 8 + mp * 2 + h;
            float4 o0, o1;
            o0.x = ((float*)&acc[mp][0])[h] + bv0.x;
            o0.y = ((float*)&acc[mp][1])[h] + bv0.y;
            o0.z = ((float*)&acc[mp][2])[h] + bv0.z;
            o0.w = ((float*)&acc[mp][3])[h] + bv0.w;
            o1.x = ((float*)&acc[mp][4])[h] + bv1.x;
            o1.y = ((float*)&acc[mp][5])[h] + bv1.y;
            o1.z = ((float*)&acc[mp][6])[h] + bv1.z;
            o1.w = ((float*)&acc[mp][7])[h] + bv1.w;
            *(float4*)&g_Gx[(size_t)r * NG + nb + nt * 8]     = o0;
            *(float4*)&g_Gx[(size_t)r * NG + nb + nt * 8 + 4] = o1;
        }
    }
}

// =====================================================================
// Phase 2: clustered recurrence (R9 verbatim — best known: 7996us).
// Cluster (8 CTAs) owns 2 batches; CTA rank owns h-cols [32r,32r+32);
// recurrent weights in REGISTERS; h exchanged via DSMEM; cluster barrier.
// =====================================================================
__global__ void __launch_bounds__(256, 1) __cluster_dims__(CLC, 1, 1)
lstm_rec(const float* __restrict__ W,
         const int* __restrict__ seq_lens,
         const float* __restrict__ c_in,
         const float* __restrict__ h_in,
         float* __restrict__ out) {
    __shared__ __align__(16) ull hsd[2][HID][2];   // duplicated h pairs, 8KB
    __shared__ __align__(16) ull part[8][32][4];   // k-partials, 8KB
    __shared__ float gred[2][128];                 // reduced gates [b][gc]

    int tid = threadIdx.x;
    int lane = tid & 31, wrp = tid >> 5;
    unsigned rank;
    asm("mov.u32 %0, %%cluster_ctarank;" : "=r"(rank));
    int cid = blockIdx.x >> 3;          // cluster id = batch group
    int b0 = cid * 2;

    // ---- weight-stationary registers: 32 k x 4 gate cols per thread ----
    ull wreg[32][2];
    {
        int gc4 = lane * 4;
        int n = (gc4 >> 5) * 256 + (int)rank * 32 + (gc4 & 31);
#pragma unroll
        for (int kk = 0; kk < 32; ++kk) {
            int k = wrp * 32 + kk;
            float4 w4 = *(const float4*)&W[(size_t)(DIN + k) * NG + n];
            float2 p0 = make_float2(w4.x, w4.y);
            float2 p1 = make_float2(w4.z, w4.w);
            wreg[kk][0] = *(ull*)&p0;
            wreg[kk][1] = *(ull*)&p1;
        }
    }

    // ---- init hsd[0] with full h(0) (local copy from gmem) ----
    {
        int k = tid;
        hsd[0][k][0] = dupf(h_in[b0 * HID + k]);
        hsd[0][k][1] = dupf(h_in[(b0 + 1) * HID + k]);
    }

    // ---- act-thread state (tid < 64): (hl, bb) ----
    int hl = tid & 31, bb = tid >> 5;
    int n_act = (int)rank * 32 + hl;
    float creg = 0.f, hreg = 0.f;
    int slen = 0;
    if (tid < 64) {
        creg = c_in[(b0 + bb) * HID + n_act];
        hreg = h_in[(b0 + bb) * HID + n_act];
        slen = seq_lens[b0 + bb];
    }
    __syncthreads();

    float* outLL = out + (size_t)BATCH * T_LEN * AOUT;
    unsigned laddr0 = smem_u32(&hsd[0][n_act][bb]);
    unsigned laddr1 = smem_u32(&hsd[1][n_act][bb]);

#pragma unroll 1
    for (int t = 0; t < T_LEN; ++t) {
        int cur = t & 1;

        // prefetch Gx (consumed ~1000 cyc later at activation)
        float gx0 = 0.f, gx1 = 0.f, gx2 = 0.f, gx3 = 0.f;
        if (tid < 64) {
            const float* gp = g_Gx + ((size_t)(t * 32 + b0 + bb)) * NG + n_act;
            gx0 = gp[0];
            gx1 = gp[256];
            gx2 = gp[512];
            gx3 = gp[768];
        }

        // ---- h @ Wh: register weights, broadcast LDS of duplicated h ----
        ull a0 = 0, a1 = 0, a2 = 0, a3 = 0;
#pragma unroll
        for (int kk = 0; kk < 32; ++kk) {
            int k = wrp * 32 + kk;
            ulonglong2 h2 = *(const ulonglong2*)&hsd[cur][k][0];
            a0 = fma2(h2.x, wreg[kk][0], a0);
            a1 = fma2(h2.x, wreg[kk][1], a1);
            a2 = fma2(h2.y, wreg[kk][0], a2);
            a3 = fma2(h2.y, wreg[kk][1], a3);
        }
        ulonglong2 s01 = {a0, a1};
        ulonglong2 s23 = {a2, a3};
        *(ulonglong2*)&part[wrp][lane][0] = s01;
        *(ulonglong2*)&part[wrp][lane][2] = s23;
        __syncthreads();

        // ---- cross-warp k-reduction: 256 threads, one gate value each ----
        {
            int l = tid >> 3, c = (tid >> 1) & 3, h = tid & 1;
            float s = 0.f;
#pragma unroll
            for (int w = 0; w < 8; ++w)
                s += ((const float*)&part[w][l][c])[h];
            int gc = 4 * l + 2 * (c & 1) + h;
            gred[c >> 1][gc] = s;
        }
        __syncthreads();

        // ---- activations + state update + DSMEM h broadcast ----
        float outv = 0.f;
        if (tid < 64) {
            float gi = gred[bb][hl]      + gx0;
            float gj = gred[bb][32 + hl] + gx1;
            float gf = gred[bb][64 + hl] + gx2;
            float go = gred[bb][96 + hl] + gx3;
            float sf = sigm(gf + 1.f);   // FORGET_BIAS = 1
            float si = sigm(gi);
            float so = sigm(go);
            float nc = creg * sf + si * tanh_e(gj);
            float nh = tanh_e(nc) * so;
            bool mvalid = (t < slen);
            if (mvalid) { creg = nc; hreg = nh; }
            outv = mvalid ? nh : 0.f;

            ull hv = dupf(hreg);
            unsigned laddr = cur ? laddr0 : laddr1;   // write buf cur^1
#pragma unroll
            for (int pr = 0; pr < CLC; ++pr) {
                unsigned ra;
                asm volatile("mapa.shared::cluster.u32 %0, %1, %2;"
                             : "=r"(ra) : "r"(laddr), "r"(pr));
                asm volatile("st.shared::cluster.b64 [%0], %1;"
                             :: "r"(ra), "l"(hv) : "memory");
            }
        }

        asm volatile("barrier.cluster.arrive.aligned;" ::: "memory");
        // hidden behind peers' arrival:
        if (tid < 64)
            outLL[((size_t)(b0 + bb) * T_LEN + t) * HID + n_act] = outv;
        asm volatile("barrier.cluster.wait.aligned;" ::: "memory");
    }

    if (tid < 64) {   // finals
        float* cf = out + (size_t)BATCH * T_LEN * AOUT + (size_t)BATCH * T_LEN * HID;
        float* hf = cf + BATCH * HID;
        cf[(b0 + bb) * HID + n_act] = creg;
        hf[(b0 + bb) * HID + n_act] = hreg;
    }
}

// =====================================================================
// Phase 3: logits = last_layer @ W_out + b_out.
// =====================================================================
#define PROJ_TPB 288
__global__ void __launch_bounds__(PROJ_TPB) proj_kernel(const float* __restrict__ LL,
                                                        const float* __restrict__ Wo,
                                                        const float* __restrict__ bo,
                                                        float* __restrict__ logits,
                                                        int tiles_per_block) {
    __shared__ float Wsm[256 * 18];
    __shared__ float Lsm[16 * 257];

    int tid = threadIdx.x;
    for (int i = tid; i < 256 * 18; i += PROJ_TPB) Wsm[i] = Wo[i];
    int r = tid / 18;
    int a = tid - r * 18;
    float bv = bo[a];

    for (int tile = 0; tile < tiles_per_block; ++tile) {
        int rbase = (blockIdx.x * tiles_per_block + tile) * 16;
        __syncthreads();
        for (int i = tid; i < 16 * 256; i += PROJ_TPB) {
            int rr = i >> 8, c = i & 255;
            Lsm[rr * 257 + c] = LL[(size_t)rbase * 256 + i];
        }
        __syncthreads();
        float acc = 0.f;
        const float* lr = &Lsm[r * 257];
#pragma unroll 8
        for (int h = 0; h < 256; ++h)
            acc = fmaf(lr[h], Wsm[h * 18 + a], acc);
        logits[(size_t)(rbase + r) * AOUT + a] = acc + bv;
    }
}

// =====================================================================
extern "C" void kernel_launch(void* const* d_in, const int* in_sizes, int n_in,
                              void* d_out, int out_size) {
    const float* x        = (const float*)d_in[0];
    const int*   seq_lens = (const int*)  d_in[1];
    const float* c_in     = (const float*)d_in[2];
    const float* h_in     = (const float*)d_in[3];
    const float* W        = (const float*)d_in[4];
    const float* b        = (const float*)d_in[5];
    const float* W_out    = (const float*)d_in[6];
    const float* b_out    = (const float*)d_in[7];
    float* out = (float*)d_out;

    // Phase 1: input GEMM for all timesteps (128n x 128m tiles)
    gemm_x<<<dim3(8, 512), 256>>>(x, W, b);

    // Phase 2: clustered recurrence (writes last_layer, c_fin, h_fin)
    lstm_rec<<<GBLK, 256>>>(W, seq_lens, c_in, h_in, out);

    // Phase 3: output projection (reads last_layer from out)
    const float* LL = out + (size_t)BATCH * T_LEN * AOUT;
    proj_kernel<<<512, PROJ_TPB>>>(LL, W_out, b_out, out, 8);
}

// round 13
// speedup vs baseline: 1.1644x; 1.1043x over previous
#include <cuda_runtime.h>
#include <cstdint>
#include <math.h>

#define T_LEN 2048
#define BATCH 32
#define DIN   256
#define HID   256
#define NG    1024   // 4*HID
#define AOUT  18
#define CLC   8      // CTAs per cluster
#define GBLK  128    // 16 rec clusters x 8 CTAs
#define NGEMM 4096   // 8 x-tiles x 512 y-tiles
#define NYG   512    // y groups (128 rows = 4 timesteps each)

typedef unsigned long long ull;

// ---------------- device scratch (no allocs allowed) ----------------
__device__ float g_Gx[(size_t)T_LEN * BATCH * NG];   // [r = t*32+b][n]  (256 MiB)
__device__ unsigned g_rdy[NYG];                      // per-y-group tile counters

// packed f32x2 FMA (SASS FFMA2): 2 fp32 FMAs per instruction
__device__ __forceinline__ ull fma2(ull a, ull b, ull c) {
    ull d;
    asm("fma.rn.f32x2 %0, %1, %2, %3;" : "=l"(d) : "l"(a), "l"(b), "l"(c));
    return d;
}
__device__ __forceinline__ ull dupf(float v) {
    unsigned u = __float_as_uint(v);
    return (ull)u | ((ull)u << 32);
}
__device__ __forceinline__ float sigm(float z) { return 1.f / (1.f + __expf(-z)); }
__device__ __forceinline__ float tanh_e(float z) { return 2.f / (1.f + __expf(-2.f * z)) - 1.f; }

__device__ __forceinline__ unsigned smem_u32(const void* p) {
    unsigned a;
    asm("{ .reg .u64 t; cvta.to.shared.u64 t, %1; cvt.u32.u64 %0, t; }"
        : "=r"(a) : "l"(p));
    return a;
}

// =====================================================================
// counter reset (graph-replay determinism)
// =====================================================================
__global__ void zero_rdy() { g_rdy[threadIdx.x] = 0u; }

// =====================================================================
// GEMM body (R11-verbatim math): tile 128m x 128n, ktile 8, thread tile
// 8m x 8n, double-buffered smem. Signals g_rdy[y] when its tile lands.
// =====================================================================
__device__ __forceinline__ void gemm_body(char* raw, int bid2,
                                          const float* __restrict__ x,
                                          const float* __restrict__ W,
                                          const float* __restrict__ bias) {
    float* As  = (float*)raw;             // [2][8*128]  8KB
    float* Bsd = (float*)(raw + 8192);    // [2][8*256] 16KB

    int tid = threadIdx.x;
    int mt = tid & 15, nt = tid >> 4;
    int bx = bid2 & 7, by = bid2 >> 3;
    int rbase = by * 128;
    int nb = bx * 128;

    int row = tid >> 1, half = tid & 1;
    int rr = rbase + row;
    int bB = rr & 31, tT = rr >> 5;
    const float* xbase = x + ((size_t)bB * T_LEN + tT) * DIN + half * 4;
    int wk = tid >> 5, wn = (tid & 31) * 4;
    const float* wbase = W + (size_t)wk * NG + nb + wn;

    float4 xa, wv;
    ull acc[4][8];
#pragma unroll
    for (int i = 0; i < 4; ++i)
#pragma unroll
        for (int j = 0; j < 8; ++j) acc[i][j] = 0ull;

    xa = *(const float4*)(xbase);
    wv = *(const float4*)(wbase);

#define STASH(buf)                                                        \
    {                                                                     \
        float* A = As + (buf) * 1024;                                     \
        int ko = half * 4;                                                \
        A[(ko + 0) * 128 + row] = xa.x; A[(ko + 1) * 128 + row] = xa.y;   \
        A[(ko + 2) * 128 + row] = xa.z; A[(ko + 3) * 128 + row] = xa.w;   \
        float* Bd = Bsd + (buf) * 2048;                                   \
        float4 d0 = make_float4(wv.x, wv.x, wv.y, wv.y);                  \
        float4 d1 = make_float4(wv.z, wv.z, wv.w, wv.w);                  \
        *(float4*)&Bd[wk * 256 + wn * 2]     = d0;                        \
        *(float4*)&Bd[wk * 256 + wn * 2 + 4] = d1;                        \
    }

    STASH(0);
    __syncthreads();

    for (int kt = 0; kt < 32; ++kt) {
        int buf = kt & 1;
        if (kt < 31) {
            xa = *(const float4*)(xbase + (kt + 1) * 8);
            wv = *(const float4*)(wbase + (size_t)(kt + 1) * 8 * NG);
        }
        const float* A = As + buf * 1024;
        const float* Bd = Bsd + buf * 2048;
#pragma unroll
        for (int k = 0; k < 8; ++k) {
            ulonglong2 a01 = *(const ulonglong2*)&A[k * 128 + mt * 8];
            ulonglong2 a23 = *(const ulonglong2*)&A[k * 128 + mt * 8 + 4];
            ulonglong2 b01 = *(const ulonglong2*)&Bd[k * 256 + nt * 16];
            ulonglong2 b23 = *(const ulonglong2*)&Bd[k * 256 + nt * 16 + 4];
            ulonglong2 b45 = *(const ulonglong2*)&Bd[k * 256 + nt * 16 + 8];
            ulonglong2 b67 = *(const ulonglong2*)&Bd[k * 256 + nt * 16 + 12];
            ull am[4] = {a01.x, a01.y, a23.x, a23.y};
            ull bd[8] = {b01.x, b01.y, b23.x, b23.y, b45.x, b45.y, b67.x, b67.y};
#pragma unroll
            for (int mp = 0; mp < 4; ++mp)
#pragma unroll
                for (int nn = 0; nn < 8; ++nn)
                    acc[mp][nn] = fma2(am[mp], bd[nn], acc[mp][nn]);
        }
        if (kt < 31) {
            STASH(buf ^ 1);
            __syncthreads();
        }
    }
#undef STASH

    float4 bv0 = *(const float4*)&bias[nb + nt * 8];
    float4 bv1 = *(const float4*)&bias[nb + nt * 8 + 4];
#pragma unroll
    for (int mp = 0; mp < 4; ++mp) {
#pragma unroll
        for (int h = 0; h < 2; ++h) {
            int r = rbase + mt * 8 + mp * 2 + h;
            float4 o0, o1;
            o0.x = ((float*)&acc[mp][0])[h] + bv0.x;
            o0.y = ((float*)&acc[mp][1])[h] + bv0.y;
            o0.z = ((float*)&acc[mp][2])[h] + bv0.z;
            o0.w = ((float*)&acc[mp][3])[h] + bv0.w;
            o1.x = ((float*)&acc[mp][4])[h] + bv1.x;
            o1.y = ((float*)&acc[mp][5])[h] + bv1.y;
            o1.z = ((float*)&acc[mp][6])[h] + bv1.z;
            o1.w = ((float*)&acc[mp][7])[h] + bv1.w;
            *(float4*)&g_Gx[(size_t)r * NG + nb + nt * 8]     = o0;
            *(float4*)&g_Gx[(size_t)r * NG + nb + nt * 8 + 4] = o1;
        }
    }

    // publish: all stores visible, then count this tile for y group `by`
    __threadfence();
    __syncthreads();
    if (tid == 0) atomicAdd(&g_rdy[by], 1u);
}

// =====================================================================
// Recurrence body (R9-verbatim sync/math) + Gx readiness gate every
// 4th step (amortized ~65cyc/step; live only while gemm still running).
// =====================================================================
__device__ __forceinline__ void rec_body(char* raw,
                                         const float* __restrict__ W,
                                         const int* __restrict__ seq_lens,
                                         const float* __restrict__ c_in,
                                         const float* __restrict__ h_in,
                                         float* __restrict__ out) {
    ull*   hsd  = (ull*)raw;                    // [2][256][2]  8KB
    ull*   part = (ull*)(raw + 8192);           // [8][32][4]   8KB
    float* gred = (float*)(raw + 16384);        // [2][128]     1KB

    int tid = threadIdx.x;
    int lane = tid & 31, wrp = tid >> 5;
    unsigned rank;
    asm("mov.u32 %0, %%cluster_ctarank;" : "=r"(rank));
    int cid = blockIdx.x >> 3;
    int b0 = cid * 2;

    // ---- weight-stationary registers: 32 k x 4 gate cols per thread ----
    ull wreg[32][2];
    {
        int gc4 = lane * 4;
        int n = (gc4 >> 5) * 256 + (int)rank * 32 + (gc4 & 31);
#pragma unroll
        for (int kk = 0; kk < 32; ++kk) {
            int k = wrp * 32 + kk;
            float4 w4 = *(const float4*)&W[(size_t)(DIN + k) * NG + n];
            float2 p0 = make_float2(w4.x, w4.y);
            float2 p1 = make_float2(w4.z, w4.w);
            wreg[kk][0] = *(ull*)&p0;
            wreg[kk][1] = *(ull*)&p1;
        }
    }

    // ---- init hsd[0] with full h(0) ----
    {
        int k = tid;
        hsd[(0 * HID + k) * 2 + 0] = dupf(h_in[b0 * HID + k]);
        hsd[(0 * HID + k) * 2 + 1] = dupf(h_in[(b0 + 1) * HID + k]);
    }

    // ---- act-thread state (tid < 64): (hl, bb) ----
    int hl = tid & 31, bb = tid >> 5;
    int n_act = (int)rank * 32 + hl;
    float creg = 0.f, hreg = 0.f;
    int slen = 0;
    if (tid < 64) {
        creg = c_in[(b0 + bb) * HID + n_act];
        hreg = h_in[(b0 + bb) * HID + n_act];
        slen = seq_lens[b0 + bb];
    }
    __syncthreads();

    float* outLL = out + (size_t)BATCH * T_LEN * AOUT;
    unsigned laddr0 = smem_u32(&hsd[(0 * HID + n_act) * 2 + bb]);
    unsigned laddr1 = smem_u32(&hsd[(1 * HID + n_act) * 2 + bb]);

#pragma unroll 1
    for (int t = 0; t < T_LEN; ++t) {
        int cur = t & 1;

        // ---- Gx readiness gate (every 4th step) ----
        if ((t & 3) == 0) {
            if (tid == 0) {
                unsigned v;
                do {
                    asm volatile("ld.acquire.gpu.global.u32 %0, [%1];"
                                 : "=r"(v) : "l"(&g_rdy[t >> 2]) : "memory");
                } while (v < 8u);
            }
            __syncthreads();
        }

        // prefetch Gx (consumed after reduction)
        float gx0 = 0.f, gx1 = 0.f, gx2 = 0.f, gx3 = 0.f;
        if (tid < 64) {
            const float* gp = g_Gx + ((size_t)(t * 32 + b0 + bb)) * NG + n_act;
            gx0 = gp[0];
            gx1 = gp[256];
            gx2 = gp[512];
            gx3 = gp[768];
        }

        // ---- h @ Wh: register weights, broadcast LDS of duplicated h ----
        ull a0 = 0, a1 = 0, a2 = 0, a3 = 0;
#pragma unroll
        for (int kk = 0; kk < 32; ++kk) {
            int k = wrp * 32 + kk;
            ulonglong2 h2 = *(const ulonglong2*)&hsd[(cur * HID + k) * 2];
            a0 = fma2(h2.x, wreg[kk][0], a0);
            a1 = fma2(h2.x, wreg[kk][1], a1);
            a2 = fma2(h2.y, wreg[kk][0], a2);
            a3 = fma2(h2.y, wreg[kk][1], a3);
        }
        ulonglong2 s01 = {a0, a1};
        ulonglong2 s23 = {a2, a3};
        *(ulonglong2*)&part[(wrp * 32 + lane) * 4]     = s01;
        *(ulonglong2*)&part[(wrp * 32 + lane) * 4 + 2] = s23;
        __syncthreads();

        // ---- cross-warp k-reduction: 256 threads, one gate value each ----
        {
            int l = tid >> 3, c = (tid >> 1) & 3, h = tid & 1;
            float s = 0.f;
#pragma unroll
            for (int w = 0; w < 8; ++w)
                s += ((const float*)&part[(w * 32 + l) * 4 + c])[h];
            int gc = 4 * l + 2 * (c & 1) + h;
            gred[(c >> 1) * 128 + gc] = s;
        }
        __syncthreads();

        // ---- activations + state update + DSMEM h broadcast ----
        float outv = 0.f;
        if (tid < 64) {
            float gi = gred[bb * 128 + hl]      + gx0;
            float gj = gred[bb * 128 + 32 + hl] + gx1;
            float gf = gred[bb * 128 + 64 + hl] + gx2;
            float go = gred[bb * 128 + 96 + hl] + gx3;
            float sf = sigm(gf + 1.f);   // FORGET_BIAS = 1
            float si = sigm(gi);
            float so = sigm(go);
            float nc = creg * sf + si * tanh_e(gj);
            float nh = tanh_e(nc) * so;
            bool mvalid = (t < slen);
            if (mvalid) { creg = nc; hreg = nh; }
            outv = mvalid ? nh : 0.f;

            ull hv = dupf(hreg);
            unsigned laddr = cur ? laddr0 : laddr1;   // write buf cur^1
#pragma unroll
            for (int pr = 0; pr < CLC; ++pr) {
                unsigned ra;
                asm volatile("mapa.shared::cluster.u32 %0, %1, %2;"
                             : "=r"(ra) : "r"(laddr), "r"(pr));
                asm volatile("st.shared::cluster.b64 [%0], %1;"
                             :: "r"(ra), "l"(hv) : "memory");
            }
        }

        asm volatile("barrier.cluster.arrive.aligned;" ::: "memory");
        if (tid < 64)
            outLL[((size_t)(b0 + bb) * T_LEN + t) * HID + n_act] = outv;
        asm volatile("barrier.cluster.wait.aligned;" ::: "memory");
    }

    if (tid < 64) {   // finals
        float* cf = out + (size_t)BATCH * T_LEN * AOUT + (size_t)BATCH * T_LEN * HID;
        float* hf = cf + BATCH * HID;
        cf[(b0 + bb) * HID + n_act] = creg;
        hf[(b0 + bb) * HID + n_act] = hreg;
    }
}

// =====================================================================
// Fused launch: blocks [0,128) = recurrence clusters, [128, 4224) = gemm.
// 2 CTAs/SM -> each rec CTA shares its SM with a streaming gemm CTA.
// =====================================================================
__global__ void __launch_bounds__(256, 2) __cluster_dims__(CLC, 1, 1)
fused(const float* __restrict__ x,
      const float* __restrict__ W,
      const float* __restrict__ bias,
      const int* __restrict__ seq_lens,
      const float* __restrict__ c_in,
      const float* __restrict__ h_in,
      float* __restrict__ out) {
    __shared__ __align__(16) char raw[24 * 1024];
    if (blockIdx.x < GBLK)
        rec_body(raw, W, seq_lens, c_in, h_in, out);
    else
        gemm_body(raw, blockIdx.x - GBLK, x, W, bias);
}

// =====================================================================
// Phase 3: logits = last_layer @ W_out + b_out.
// =====================================================================
#define PROJ_TPB 288
__global__ void __launch_bounds__(PROJ_TPB) proj_kernel(const float* __restrict__ LL,
                                                        const float* __restrict__ Wo,
                                                        const float* __restrict__ bo,
                                                        float* __restrict__ logits,
                                                        int tiles_per_block) {
    __shared__ float Wsm[256 * 18];
    __shared__ float Lsm[16 * 257];

    int tid = threadIdx.x;
    for (int i = tid; i < 256 * 18; i += PROJ_TPB) Wsm[i] = Wo[i];
    int r = tid / 18;
    int a = tid - r * 18;
    float bv = bo[a];

    for (int tile = 0; tile < tiles_per_block; ++tile) {
        int rbase = (blockIdx.x * tiles_per_block + tile) * 16;
        __syncthreads();
        for (int i = tid; i < 16 * 256; i += PROJ_TPB) {
            int rr = i >> 8, c = i & 255;
            Lsm[rr * 257 + c] = LL[(size_t)rbase * 256 + i];
        }
        __syncthreads();
        float acc = 0.f;
        const float* lr = &Lsm[r * 257];
#pragma unroll 8
        for (int h = 0; h < 256; ++h)
            acc = fmaf(lr[h], Wsm[h * 18 + a], acc);
        logits[(size_t)(rbase + r) * AOUT + a] = acc + bv;
    }
}

// =====================================================================
extern "C" void kernel_launch(void* const* d_in, const int* in_sizes, int n_in,
                              void* d_out, int out_size) {
    const float* x        = (const float*)d_in[0];
    const int*   seq_lens = (const int*)  d_in[1];
    const float* c_in     = (const float*)d_in[2];
    const float* h_in     = (const float*)d_in[3];
    const float* W        = (const float*)d_in[4];
    const float* b        = (const float*)d_in[5];
    const float* W_out    = (const float*)d_in[6];
    const float* b_out    = (const float*)d_in[7];
    float* out = (float*)d_out;

    // reset readiness counters (graph-replay determinism)
    zero_rdy<<<1, NYG>>>();

    // fused: recurrence (blocks 0..127) + input GEMM (blocks 128..4223)
    fused<<<GBLK + NGEMM, 256>>>(x, W, b, seq_lens, c_in, h_in, out);

    // output projection (reads last_layer from out)
    const float* LL = out + (size_t)BATCH * T_LEN * AOUT;
    proj_kernel<<<512, PROJ_TPB>>>(LL, W_out, b_out, out, 8);
}

// round 17
// speedup vs baseline: 1.2755x; 1.0954x over previous
#include <cuda_runtime.h>
#include <cstdint>
#include <math.h>

#define T_LEN 2048
#define BATCH 32
#define DIN   256
#define HID   256
#define NG    1024   // 4*HID
#define AOUT  18
#define CLC   8      // CTAs per cluster
#define GBLK  128    // 16 rec clusters x 8 CTAs
#define NGEMM 4096   // 8 x-tiles x 512 y-tiles
#define NYG   512    // y groups (128 rows = 4 timesteps each)
#define TXB   4096   // 8 ranks x 64 threads x 8B per phase

typedef unsigned long long ull;

// ---------------- device scratch (no allocs allowed) ----------------
__device__ float g_Gx[(size_t)T_LEN * BATCH * NG];   // [r = t*32+b][n]  (256 MiB)
__device__ unsigned g_rdy[NYG];                      // per-y-group tile counters

__device__ __forceinline__ ull fma2(ull a, ull b, ull c) {
    ull d;
    asm("fma.rn.f32x2 %0, %1, %2, %3;" : "=l"(d) : "l"(a), "l"(b), "l"(c));
    return d;
}
__device__ __forceinline__ ull dupf(float v) {
    unsigned u = __float_as_uint(v);
    return (ull)u | ((ull)u << 32);
}
__device__ __forceinline__ float sigm(float z) { return 1.f / (1.f + __expf(-z)); }
__device__ __forceinline__ float tanh_e(float z) { return 2.f / (1.f + __expf(-2.f * z)) - 1.f; }

__device__ __forceinline__ unsigned smem_u32(const void* p) {
    unsigned a;
    asm("{ .reg .u64 t; cvta.to.shared.u64 t, %1; cvt.u32.u64 %0, t; }"
        : "=r"(a) : "l"(p));
    return a;
}
__device__ __forceinline__ void mbar_init(unsigned mb, unsigned cnt) {
    asm volatile("mbarrier.init.shared.b64 [%0], %1;" :: "r"(mb), "r"(cnt) : "memory");
}
__device__ __forceinline__ void mbar_expect(unsigned mb, unsigned tx) {
    asm volatile("mbarrier.arrive.expect_tx.shared.b64 _, [%0], %1;"
                 :: "r"(mb), "r"(tx) : "memory");
}
__device__ __forceinline__ void mbar_wait(unsigned mb, unsigned parity) {
    unsigned done;
    do {
        asm volatile(
            "{ .reg .pred p;\n\t"
            "mbarrier.try_wait.parity.acquire.cluster.shared::cta.b64 p, [%1], %2, 0x989680;\n\t"
            "selp.b32 %0, 1, 0, p; }"
            : "=r"(done) : "r"(mb), "r"(parity) : "memory");
    } while (!done);
}

// =====================================================================
__global__ void zero_rdy() { g_rdy[threadIdx.x] = 0u; }

// =====================================================================
// GEMM body (R13-verbatim): tile 128m x 128n, ktile 8, thread tile 8m x 8n.
// =====================================================================
__device__ __forceinline__ void gemm_body(char* raw, int bid2,
                                          const float* __restrict__ x,
                                          const float* __restrict__ W,
                                          const float* __restrict__ bias) {
    float* As  = (float*)raw;             // [2][8*128]  8KB
    float* Bsd = (float*)(raw + 8192);    // [2][8*256] 16KB

    int tid = threadIdx.x;
    int mt = tid & 15, nt = tid >> 4;
    int bx = bid2 & 7, by = bid2 >> 3;
    int rbase = by * 128;
    int nb = bx * 128;

    int row = tid >> 1, half = tid & 1;
    int rr = rbase + row;
    int bB = rr & 31, tT = rr >> 5;
    const float* xbase = x + ((size_t)bB * T_LEN + tT) * DIN + half * 4;
    int wk = tid >> 5, wn = (tid & 31) * 4;
    const float* wbase = W + (size_t)wk * NG + nb + wn;

    float4 xa, wv;
    ull acc[4][8];
#pragma unroll
    for (int i = 0; i < 4; ++i)
#pragma unroll
        for (int j = 0; j < 8; ++j) acc[i][j] = 0ull;

    xa = *(const float4*)(xbase);
    wv = *(const float4*)(wbase);

#define STASH(buf)                                                        \
    {                                                                     \
        float* A = As + (buf) * 1024;                                     \
        int ko = half * 4;                                                \
        A[(ko + 0) * 128 + row] = xa.x; A[(ko + 1) * 128 + row] = xa.y;   \
        A[(ko + 2) * 128 + row] = xa.z; A[(ko + 3) * 128 + row] = xa.w;   \
        float* Bd = Bsd + (buf) * 2048;                                   \
        float4 d0 = make_float4(wv.x, wv.x, wv.y, wv.y);                  \
        float4 d1 = make_float4(wv.z, wv.z, wv.w, wv.w);                  \
        *(float4*)&Bd[wk * 256 + wn * 2]     = d0;                        \
        *(float4*)&Bd[wk * 256 + wn * 2 + 4] = d1;                        \
    }

    STASH(0);
    __syncthreads();

    for (int kt = 0; kt < 32; ++kt) {
        int buf = kt & 1;
        if (kt < 31) {
            xa = *(const float4*)(xbase + (kt + 1) * 8);
            wv = *(const float4*)(wbase + (size_t)(kt + 1) * 8 * NG);
        }
        const float* A = As + buf * 1024;
        const float* Bd = Bsd + buf * 2048;
#pragma unroll
        for (int k = 0; k < 8; ++k) {
            ulonglong2 a01 = *(const ulonglong2*)&A[k * 128 + mt * 8];
            ulonglong2 a23 = *(const ulonglong2*)&A[k * 128 + mt * 8 + 4];
            ulonglong2 b01 = *(const ulonglong2*)&Bd[k * 256 + nt * 16];
            ulonglong2 b23 = *(const ulonglong2*)&Bd[k * 256 + nt * 16 + 4];
            ulonglong2 b45 = *(const ulonglong2*)&Bd[k * 256 + nt * 16 + 8];
            ulonglong2 b67 = *(const ulonglong2*)&Bd[k * 256 + nt * 16 + 12];
            ull am[4] = {a01.x, a01.y, a23.x, a23.y};
            ull bd[8] = {b01.x, b01.y, b23.x, b23.y, b45.x, b45.y, b67.x, b67.y};
#pragma unroll
            for (int mp = 0; mp < 4; ++mp)
#pragma unroll
                for (int nn = 0; nn < 8; ++nn)
                    acc[mp][nn] = fma2(am[mp], bd[nn], acc[mp][nn]);
        }
        if (kt < 31) {
            STASH(buf ^ 1);
            __syncthreads();
        }
    }
#undef STASH

    float4 bv0 = *(const float4*)&bias[nb + nt * 8];
    float4 bv1 = *(const float4*)&bias[nb + nt * 8 + 4];
#pragma unroll
    for (int mp = 0; mp < 4; ++mp) {
#pragma unroll
        for (int h = 0; h < 2; ++h) {
            int r = rbase + mt * 8 + mp * 2 + h;
            float4 o0, o1;
            o0.x = ((float*)&acc[mp][0])[h] + bv0.x;
            o0.y = ((float*)&acc[mp][1])[h] + bv0.y;
            o0.z = ((float*)&acc[mp][2])[h] + bv0.z;
            o0.w = ((float*)&acc[mp][3])[h] + bv0.w;
            o1.x = ((float*)&acc[mp][4])[h] + bv1.x;
            o1.y = ((float*)&acc[mp][5])[h] + bv1.y;
            o1.z = ((float*)&acc[mp][6])[h] + bv1.z;
            o1.w = ((float*)&acc[mp][7])[h] + bv1.w;
            *(float4*)&g_Gx[(size_t)r * NG + nb + nt * 8]     = o0;
            *(float4*)&g_Gx[(size_t)r * NG + nb + nt * 8 + 4] = o1;
        }
    }

    __threadfence();
    __syncthreads();
    if (tid == 0) atomicAdd(&g_rdy[by], 1u);
}

// =====================================================================
// Recurrence body: mbarrier tx-sync v2.
//  - all h writes (incl. self) via st.async -> tx-counted on each CTA's
//    per-buffer mbarrier; all 256 threads try_wait directly (no bar.cluster,
//    no syncthreads at the wait).
//  - Gx gate + prefetch hoisted before the wait (overlaps DRAM + skew).
// =====================================================================
__device__ __forceinline__ void rec_body(char* raw,
                                         const float* __restrict__ W,
                                         const int* __restrict__ seq_lens,
                                         const float* __restrict__ c_in,
                                         const float* __restrict__ h_in,
                                         float* __restrict__ out) {
    ull*   hsd  = (ull*)raw;                    // [2][256][2]  8KB
    ull*   part = (ull*)(raw + 8192);           // [8][32][4]   8KB
    float* gred = (float*)(raw + 16384);        // [2][128]     1KB
    ull*   mbars = (ull*)(raw + 16384 + 1024);  // [2] mbarriers

    int tid = threadIdx.x;
    int lane = tid & 31, wrp = tid >> 5;
    unsigned rank;
    asm("mov.u32 %0, %%cluster_ctarank;" : "=r"(rank));
    int cid = blockIdx.x >> 3;
    int b0 = cid * 2;

    unsigned mb0 = smem_u32(&mbars[0]);
    unsigned mb1 = smem_u32(&mbars[1]);

    // ---- weight-stationary registers: 32 k x 4 gate cols per thread ----
    ull wreg[32][2];
    {
        int gc4 = lane * 4;
        int n = (gc4 >> 5) * 256 + (int)rank * 32 + (gc4 & 31);
#pragma unroll
        for (int kk = 0; kk < 32; ++kk) {
            int k = wrp * 32 + kk;
            float4 w4 = *(const float4*)&W[(size_t)(DIN + k) * NG + n];
            float2 p0 = make_float2(w4.x, w4.y);
            float2 p1 = make_float2(w4.z, w4.w);
            wreg[kk][0] = *(ull*)&p0;
            wreg[kk][1] = *(ull*)&p1;
        }
    }

    // ---- init hsd[0] + mbarriers ----
    {
        int k = tid;
        hsd[(0 * HID + k) * 2 + 0] = dupf(h_in[b0 * HID + k]);
        hsd[(0 * HID + k) * 2 + 1] = dupf(h_in[(b0 + 1) * HID + k]);
    }
    if (tid == 0) {
        mbar_init(mb0, 1);
        mbar_init(mb1, 1);
    }

    int hl = tid & 31, bb = tid >> 5;
    int n_act = (int)rank * 32 + hl;
    float creg = 0.f, hreg = 0.f;
    int slen = 0;
    if (tid < 64) {
        creg = c_in[(b0 + bb) * HID + n_act];
        hreg = h_in[(b0 + bb) * HID + n_act];
        slen = seq_lens[b0 + bb];
    }
    __syncthreads();
    // mbarrier inits visible cluster-wide before any peer st.async
    asm volatile("barrier.cluster.arrive.aligned;" ::: "memory");
    asm volatile("barrier.cluster.wait.aligned;" ::: "memory");

    if (tid == 0) {            // pre-arm: writes of step 0 (mb1), step 1 (mb0)
        mbar_expect(mb1, TXB);
        mbar_expect(mb0, TXB);
    }

    float* outLL = out + (size_t)BATCH * T_LEN * AOUT;
    unsigned laddr0 = smem_u32(&hsd[(0 * HID + n_act) * 2 + bb]);
    unsigned laddr1 = smem_u32(&hsd[(1 * HID + n_act) * 2 + bb]);

#pragma unroll 1
    for (int t = 0; t < T_LEN; ++t) {
        int cur = t & 1;

        // ---- Gx gate (h-independent, overlaps the h-wait below) ----
        if ((t & 3) == 0) {
            unsigned v;
            do {
                asm volatile("ld.acquire.gpu.global.u32 %0, [%1];"
                             : "=r"(v) : "l"(&g_rdy[t >> 2]) : "memory");
            } while (v < 8u);
        }
        // ---- Gx prefetch (issued before the h-wait; DRAM latency hidden) ----
        float gx0 = 0.f, gx1 = 0.f, gx2 = 0.f, gx3 = 0.f;
        if (tid < 64) {
            const float* gp = g_Gx + ((size_t)(t * 32 + b0 + bb)) * NG + n_act;
            gx0 = gp[0];
            gx1 = gp[256];
            gx2 = gp[512];
            gx3 = gp[768];
        }

        // ---- wait for h(t) txs (all threads; no syncthreads) ----
        if (t > 0) {
            unsigned mb = cur ? mb1 : mb0;
            mbar_wait(mb, ((unsigned)(t - 1) >> 1) & 1u);
            if (tid == 0 && t + 2 < T_LEN)
                mbar_expect(mb, TXB);   // re-arm for writes at step t+1
        }

        // ---- h @ Wh: register weights, broadcast LDS of duplicated h ----
        ull a0 = 0, a1 = 0, a2 = 0, a3 = 0;
#pragma unroll
        for (int kk = 0; kk < 32; ++kk) {
            int k = wrp * 32 + kk;
            ulonglong2 h2 = *(const ulonglong2*)&hsd[(cur * HID + k) * 2];
            a0 = fma2(h2.x, wreg[kk][0], a0);
            a1 = fma2(h2.x, wreg[kk][1], a1);
            a2 = fma2(h2.y, wreg[kk][0], a2);
            a3 = fma2(h2.y, wreg[kk][1], a3);
        }
        ulonglong2 s01 = {a0, a1};
        ulonglong2 s23 = {a2, a3};
        *(ulonglong2*)&part[(wrp * 32 + lane) * 4]     = s01;
        *(ulonglong2*)&part[(wrp * 32 + lane) * 4 + 2] = s23;
        __syncthreads();

        // ---- cross-warp k-reduction ----
        {
            int l = tid >> 3, c = (tid >> 1) & 3, h = tid & 1;
            float s = 0.f;
#pragma unroll
            for (int w = 0; w < 8; ++w)
                s += ((const float*)&part[(w * 32 + l) * 4 + c])[h];
            int gc = 4 * l + 2 * (c & 1) + h;
            gred[(c >> 1) * 128 + gc] = s;
        }
        __syncthreads();

        // ---- activations + state update + st.async publish ----
        if (tid < 64) {
            float gi = gred[bb * 128 + hl]      + gx0;
            float gj = gred[bb * 128 + 32 + hl] + gx1;
            float gf = gred[bb * 128 + 64 + hl] + gx2;
            float go = gred[bb * 128 + 96 + hl] + gx3;
            float sf = sigm(gf + 1.f);   // FORGET_BIAS = 1
            float si = sigm(gi);
            float so = sigm(go);
            float nc = creg * sf + si * tanh_e(gj);
            float nh = tanh_e(nc) * so;
            bool mvalid = (t < slen);
            if (mvalid) { creg = nc; hreg = nh; }

            if (t + 1 < T_LEN) {
                ull hv = dupf(hreg);
                int nxt = cur ^ 1;
                unsigned la = nxt ? laddr1 : laddr0;
                unsigned mbl = nxt ? mb1 : mb0;
#pragma unroll
                for (int pr = 0; pr < CLC; ++pr) {
                    unsigned da, ma;
                    asm volatile("mapa.shared::cluster.u32 %0, %1, %2;"
                                 : "=r"(da) : "r"(la), "r"(pr));
                    asm volatile("mapa.shared::cluster.u32 %0, %1, %2;"
                                 : "=r"(ma) : "r"(mbl), "r"(pr));
                    asm volatile(
                        "st.async.weak.shared::cluster.mbarrier::complete_tx::bytes.b64 [%0], %1, [%2];"
                        :: "r"(da), "l"(hv), "r"(ma) : "memory");
                }
            }

            // off critical path:
            outLL[((size_t)(b0 + bb) * T_LEN + t) * HID + n_act] = mvalid ? nh : 0.f;
        }
    }

    if (tid < 64) {   // finals
        float* cf = out + (size_t)BATCH * T_LEN * AOUT + (size_t)BATCH * T_LEN * HID;
        float* hf = cf + BATCH * HID;
        cf[(b0 + bb) * HID + n_act] = creg;
        hf[(b0 + bb) * HID + n_act] = hreg;
    }

    // no in-flight st.async can target a peer after its last wait (publishes
    // end at t=T_LEN-2, consumed at t=T_LEN-1); final sync for exit safety
    asm volatile("barrier.cluster.arrive.aligned;" ::: "memory");
    asm volatile("barrier.cluster.wait.aligned;" ::: "memory");
}

// =====================================================================
__global__ void __launch_bounds__(256, 2) __cluster_dims__(CLC, 1, 1)
fused(const float* __restrict__ x,
      const float* __restrict__ W,
      const float* __restrict__ bias,
      const int* __restrict__ seq_lens,
      const float* __restrict__ c_in,
      const float* __restrict__ h_in,
      float* __restrict__ out) {
    __shared__ __align__(16) char raw[24 * 1024];
    if (blockIdx.x < GBLK)
        rec_body(raw, W, seq_lens, c_in, h_in, out);
    else
        gemm_body(raw, blockIdx.x - GBLK, x, W, bias);
}

// =====================================================================
// Phase 3: logits = last_layer @ W_out + b_out.
// =====================================================================
#define PROJ_TPB 288
__global__ void __launch_bounds__(PROJ_TPB) proj_kernel(const float* __restrict__ LL,
                                                        const float* __restrict__ Wo,
                                                        const float* __restrict__ bo,
                                                        float* __restrict__ logits,
                                                        int tiles_per_block) {
    __shared__ float Wsm[256 * 18];
    __shared__ float Lsm[16 * 257];

    int tid = threadIdx.x;
    for (int i = tid; i < 256 * 18; i += PROJ_TPB) Wsm[i] = Wo[i];
    int r = tid / 18;
    int a = tid - r * 18;
    float bv = bo[a];

    for (int tile = 0; tile < tiles_per_block; ++tile) {
        int rbase = (blockIdx.x * tiles_per_block + tile) * 16;
        __syncthreads();
        for (int i = tid; i < 16 * 256; i += PROJ_TPB) {
            int rr = i >> 8, c = i & 255;
            Lsm[rr * 257 + c] = LL[(size_t)rbase * 256 + i];
        }
        __syncthreads();
        float acc = 0.f;
        const float* lr = &Lsm[r * 257];
#pragma unroll 8
        for (int h = 0; h < 256; ++h)
            acc = fmaf(lr[h], Wsm[h * 18 + a], acc);
        logits[(size_t)(rbase + r) * AOUT + a] = acc + bv;
    }
}

// =====================================================================
extern "C" void kernel_launch(void* const* d_in, const int* in_sizes, int n_in,
                              void* d_out, int out_size) {
    const float* x        = (const float*)d_in[0];
    const int*   seq_lens = (const int*)  d_in[1];
    const float* c_in     = (const float*)d_in[2];
    const float* h_in     = (const float*)d_in[3];
    const float* W        = (const float*)d_in[4];
    const float* b        = (const float*)d_in[5];
    const float* W_out    = (const float*)d_in[6];
    const float* b_out    = (const float*)d_in[7];
    float* out = (float*)d_out;

    // reset readiness counters (graph-replay determinism)
    zero_rdy<<<1, NYG>>>();

    // fused: recurrence (blocks 0..127) + input GEMM (blocks 128..4223)
    fused<<<GBLK + NGEMM, 256>>>(x, W, b, seq_lens, c_in, h_in, out);

    // output projection (reads last_layer from out)
    const float* LL = out + (size_t)BATCH * T_LEN * AOUT;
    proj_kernel<<<512, PROJ_TPB>>>(LL, W_out, b_out, out, 8);
}